// round 5
// baseline (speedup 1.0000x reference)
#include <cuda_runtime.h>
#include <cstdint>

// Problem constants
#define BATCH    16
#define HW       (1024 * 1024)
#define GRIDX    37                 // 37*16 = 592 = 148 SMs * 4 CTAs -> one exact wave
#define NT       256
#define NQ       7                  // focal, lg, omp, tomp, t, bin, bint
#define SMOOTH   1e-6f
#define NBLOCKS  (GRIDX * BATCH)

#define NSLOT        4
#define STAGE_FLOATS 1024           // 4KB per array per stage
#define STAGE_BYTES  4096
#define NSTAGES_IMG  (HW / STAGE_FLOATS)   // 1024, divides exactly

__device__ float        g_part[BATCH * GRIDX * 8];
__device__ unsigned int g_count;    // zero-init; self-resets each launch

typedef unsigned long long ull;

// ---------- f32x2 packed helpers ----------
__device__ __forceinline__ ull pk2(float lo, float hi) {
    ull r; asm("mov.b64 %0, {%1, %2};" : "=l"(r) : "f"(lo), "f"(hi)); return r;
}
__device__ __forceinline__ void upk2(ull v, float& lo, float& hi) {
    asm("mov.b64 {%0, %1}, %2;" : "=f"(lo), "=f"(hi) : "l"(v));
}
__device__ __forceinline__ ull mul2(ull a, ull b) {
    ull r; asm("mul.rn.f32x2 %0, %1, %2;" : "=l"(r) : "l"(a), "l"(b)); return r;
}
__device__ __forceinline__ ull add2(ull a, ull b) {
    ull r; asm("add.rn.f32x2 %0, %1, %2;" : "=l"(r) : "l"(a), "l"(b)); return r;
}
__device__ __forceinline__ ull fma2(ull a, ull b, ull c) {
    ull r; asm("fma.rn.f32x2 %0, %1, %2, %3;" : "=l"(r) : "l"(a), "l"(b), "l"(c)); return r;
}
__device__ __forceinline__ float ex2a(float x) {
    float r; asm("ex2.approx.f32 %0, %1;" : "=f"(r) : "f"(x)); return r;
}
__device__ __forceinline__ float lg2a(float x) {
    float r; asm("lg2.approx.f32 %0, %1;" : "=f"(r) : "f"(x)); return r;
}
__device__ __forceinline__ float rcpa(float x) {
    float r; asm("rcp.approx.f32 %0, %1;" : "=f"(r) : "f"(x)); return r;
}

// ---------- smem / mbarrier / bulk-copy helpers ----------
__device__ __forceinline__ uint32_t smem_u32(const void* p) {
    uint32_t a;
    asm("{ .reg .u64 t; cvta.to.shared.u64 t, %1; cvt.u32.u64 %0, t; }" : "=r"(a) : "l"(p));
    return a;
}
__device__ __forceinline__ void mbar_init(uint32_t addr, uint32_t cnt) {
    asm volatile("mbarrier.init.shared.b64 [%0], %1;" :: "r"(addr), "r"(cnt) : "memory");
}
__device__ __forceinline__ void mbar_wait(uint32_t addr, uint32_t parity) {
    asm volatile(
        "{\n\t.reg .pred P;\n\t"
        "W%=:\n\t"
        "mbarrier.try_wait.parity.acquire.cta.shared::cta.b64 P, [%0], %1, 0x989680;\n\t"
        "@!P bra W%=;\n\t"
        "}" :: "r"(addr), "r"(parity) : "memory");
}
__device__ __forceinline__ void expect_tx(uint32_t addr, uint32_t bytes) {
    asm volatile("mbarrier.arrive.expect_tx.shared.b64 _, [%0], %1;"
                 :: "r"(addr), "r"(bytes) : "memory");
}
__device__ __forceinline__ void bulk_ld(uint32_t dst_smem, const void* src, uint32_t bytes,
                                        uint32_t mbar) {
    asm volatile(
        "cp.async.bulk.shared::cta.global.mbarrier::complete_tx::bytes [%0], [%1], %2, [%3];"
        :: "r"(dst_smem), "l"(src), "r"(bytes), "r"(mbar) : "memory");
}

struct Accs { ull f, lg, omp, tomp, t, bin, bint; };

// Per-pair math, t in {0,1}:
//   v = exp((1-2t)*x) ; ce = ln2*lg2(1+v) ; omp = 1-p_t = v/(1+v)
//   focal elem = (0.75-0.5t)*lg2(1+v)*omp^2      (ln2 factored in epilogue)
//   p, p*t recovered in epilogue: Sp = omp + t - 2*tomp ; Spt = t - tomp
__device__ __forceinline__ void group(Accs& A, float x0, float x1, float t0, float t1,
                                      ull Kp, ull Km2, ull ONE2, ull HALF2, ull K75, ull KNH) {
    ull x2 = pk2(x0, x1);
    ull t2 = pk2(t0, t1);
    ull c2 = fma2(t2, Km2, Kp);          // log2e * (1-2t)
    ull m2 = mul2(x2, c2);
    float m0, m1; upk2(m2, m0, m1);
    float v0 = ex2a(m0), v1 = ex2a(m1);
    ull v2 = pk2(v0, v1);
    ull s2 = add2(v2, ONE2);             // 1+v
    float s0, s1; upk2(s2, s0, s1);
    float r0 = rcpa(s0), r1 = rcpa(s1);
    float l0 = lg2a(s0), l1 = lg2a(s1);
    ull r2 = pk2(r0, r1);
    ull l2 = pk2(l0, l1);
    ull omp2 = mul2(v2, r2);             // v/(1+v)
    ull o2   = mul2(omp2, omp2);
    ull g2   = mul2(l2, o2);             // lg2(1+v)*omp^2
    ull a2   = fma2(t2, KNH, K75);       // 0.75 - 0.5t
    A.f    = fma2(a2, g2, A.f);
    A.lg   = add2(A.lg, l2);
    A.omp  = add2(A.omp, omp2);
    A.tomp = fma2(t2, omp2, A.tomp);
    A.t    = add2(A.t, t2);
    unsigned sb0 = (__float_as_uint(x0) & 0x80000000u) | 0x3F800000u;  // +-1.0f
    unsigned sb1 = (__float_as_uint(x1) & 0x80000000u) | 0x3F800000u;
    ull sgn2 = pk2(__uint_as_float(sb0), __uint_as_float(sb1));
    ull bin2 = fma2(sgn2, HALF2, HALF2); // (x>0) ? 1 : 0
    A.bin  = add2(A.bin, bin2);
    A.bint = fma2(t2, bin2, A.bint);
}

__device__ __forceinline__ float warp_sum(float v) {
    #pragma unroll
    for (int off = 16; off > 0; off >>= 1)
        v += __shfl_xor_sync(0xFFFFFFFFu, v, off);
    return v;
}

__global__ __launch_bounds__(NT, 4)
void loss_fused_kernel(const float* __restrict__ pred,
                       const float* __restrict__ gt,
                       const float* __restrict__ pred_iou,
                       float*       __restrict__ out) {
    __shared__ float4 sp[NSLOT][NT];      // pred stages: 4 x 4KB
    __shared__ float4 sg[NSLOT][NT];      // gt stages:   4 x 4KB
    __shared__ __align__(8) ull mbar[NSLOT];

    const int tid = threadIdx.x;
    const int img = blockIdx.y;
    const int cta = blockIdx.x;

    const float* pimg = pred + (size_t)img * HW;
    const float* gimg = gt   + (size_t)img * HW;

    const uint32_t mb0 = smem_u32(&mbar[0]);
    uint32_t sp_addr[NSLOT], sg_addr[NSLOT];
    #pragma unroll
    for (int s = 0; s < NSLOT; s++) {
        sp_addr[s] = smem_u32(&sp[s][0]);
        sg_addr[s] = smem_u32(&sg[s][0]);
    }

    // stages of this CTA: s = cta + j*GRIDX, j = 0..nst-1
    const int nst = (NSTAGES_IMG - cta + GRIDX - 1) / GRIDX;

    if (tid == 0) {
        #pragma unroll
        for (int s = 0; s < NSLOT; s++) mbar_init(mb0 + 8u * s, 1);
        asm volatile("fence.proxy.async.shared::cta;" ::: "memory");
    }
    __syncthreads();

    // prologue: fill up to NSLOT stages
    if (tid == 0) {
        int pre = nst < NSLOT ? nst : NSLOT;
        for (int j = 0; j < pre; j++) {
            int s = cta + j * GRIDX;
            uint32_t mb = mb0 + 8u * j;
            expect_tx(mb, 2 * STAGE_BYTES);
            bulk_ld(sp_addr[j], pimg + (size_t)s * STAGE_FLOATS, STAGE_BYTES, mb);
            bulk_ld(sg_addr[j], gimg + (size_t)s * STAGE_FLOATS, STAGE_BYTES, mb);
        }
    }

    const float LOG2E = 1.4426950408889634f;
    const ull Kp    = pk2(LOG2E, LOG2E);
    const ull Km2   = pk2(-2.0f * LOG2E, -2.0f * LOG2E);
    const ull ONE2  = pk2(1.0f, 1.0f);
    const ull HALF2 = pk2(0.5f, 0.5f);
    const ull K75   = pk2(0.75f, 0.75f);
    const ull KNH   = pk2(-0.5f, -0.5f);

    Accs A;
    A.f = A.lg = A.omp = A.tomp = A.t = A.bin = A.bint = pk2(0.0f, 0.0f);

    for (int j = 0; j < nst; j++) {
        const int slot = j & (NSLOT - 1);
        const uint32_t phase = (uint32_t)(j >> 2) & 1u;
        mbar_wait(mb0 + 8u * slot, phase);

        float4 p4 = sp[slot][tid];
        float4 g4 = sg[slot][tid];
        group(A, p4.x, p4.y, g4.x, g4.y, Kp, Km2, ONE2, HALF2, K75, KNH);
        group(A, p4.z, p4.w, g4.z, g4.w, Kp, Km2, ONE2, HALF2, K75, KNH);

        __syncthreads();   // all consumers done with this slot
        if (tid == 0 && j + NSLOT < nst) {
            int s = cta + (j + NSLOT) * GRIDX;
            uint32_t mb = mb0 + 8u * slot;
            expect_tx(mb, 2 * STAGE_BYTES);
            bulk_ld(sp_addr[slot], pimg + (size_t)s * STAGE_FLOATS, STAGE_BYTES, mb);
            bulk_ld(sg_addr[slot], gimg + (size_t)s * STAGE_FLOATS, STAGE_BYTES, mb);
        }
    }

    // collapse packed halves
    float vals[NQ];
    {
        float lo, hi;
        upk2(A.f,    lo, hi); vals[0] = lo + hi;
        upk2(A.lg,   lo, hi); vals[1] = lo + hi;
        upk2(A.omp,  lo, hi); vals[2] = lo + hi;
        upk2(A.tomp, lo, hi); vals[3] = lo + hi;
        upk2(A.t,    lo, hi); vals[4] = lo + hi;
        upk2(A.bin,  lo, hi); vals[5] = lo + hi;
        upk2(A.bint, lo, hi); vals[6] = lo + hi;
    }

    // -------- block reduction --------
    #pragma unroll
    for (int q = 0; q < NQ; q++) vals[q] = warp_sum(vals[q]);

    __shared__ float sm[NT / 32][NQ];
    const int lane = tid & 31;
    const int warp = tid >> 5;
    if (lane == 0) {
        #pragma unroll
        for (int q = 0; q < NQ; q++) sm[warp][q] = vals[q];
    }
    __syncthreads();

    __shared__ bool is_last;
    if (warp == 0) {
        #pragma unroll
        for (int q = 0; q < NQ; q++) {
            float v = (lane < NT / 32) ? sm[lane][q] : 0.0f;
            v = warp_sum(v);
            if (lane == 0) vals[q] = v;
        }
        if (lane == 0) {
            float* dst = g_part + ((size_t)img * GRIDX + blockIdx.x) * 8;
            #pragma unroll
            for (int q = 0; q < NQ; q++) dst[q] = vals[q];
            __threadfence();
            unsigned int v = atomicAdd(&g_count, 1u);
            is_last = (v == (unsigned int)(NBLOCKS - 1));
        }
    }
    __syncthreads();
    if (!is_last) return;

    // -------- epilogue: last block reduces 592 partials --------
    __shared__ float agg[BATCH][4];
    for (int b = warp; b < BATCH; b += NT / 32) {
        float s[NQ] = {0.f, 0.f, 0.f, 0.f, 0.f, 0.f, 0.f};
        for (int j = lane; j < GRIDX; j += 32) {
            const float* q = g_part + ((size_t)b * GRIDX + j) * 8;
            #pragma unroll
            for (int k = 0; k < NQ; k++) s[k] += q[k];
        }
        #pragma unroll
        for (int k = 0; k < NQ; k++) s[k] = warp_sum(s[k]);
        if (lane == 0) {
            // s: 0=focal(lg2-scaled) 1=lg 2=omp 3=tomp 4=t 5=bin 6=bint
            float Sp  = s[2] + s[4] - 2.0f * s[3];
            float Spt = s[4] - s[3];
            float dice_term = (2.0f * Spt + SMOOTH) / (Sp + s[4] + SMOOTH);
            float inter  = s[6];
            float uni    = s[5] + s[4] - s[6];
            float actual = (inter + SMOOTH) / (uni + SMOOTH);
            float d = pred_iou[b] - actual;
            agg[b][0] = s[0];
            agg[b][1] = s[1];
            agg[b][2] = dice_term;
            agg[b][3] = d * d;
        }
    }
    __syncthreads();

    if (tid == 0) {
        float fsum = 0.f, csum = 0.f, dsum = 0.f, isum = 0.f;
        #pragma unroll
        for (int b = 0; b < BATCH; b++) {
            fsum += agg[b][0];
            csum += agg[b][1];
            dsum += agg[b][2];
            isum += agg[b][3];
        }
        const float LN2  = 0.6931471805599453f;
        const float invN = 1.0f / (float)((long long)BATCH * HW);
        float focal    = LN2 * fsum * invN;
        float dice     = 1.0f - dsum / (float)BATCH;
        float boundary = LN2 * csum * invN;   // mean(ce) = 0.5 * (2*mean(ce))
        float iou_loss = 0.1f * (isum / (float)BATCH);
        out[0] = focal + dice + boundary + iou_loss;
        g_count = 0;   // reset for next graph replay
    }
}

extern "C" void kernel_launch(void* const* d_in, const int* in_sizes, int n_in,
                              void* d_out, int out_size) {
    const float* pred = (const float*)d_in[0];
    const float* gt   = (const float*)d_in[1];
    const float* piou = (const float*)d_in[2];
    float* out = (float*)d_out;

    dim3 grid(GRIDX, BATCH);
    loss_fused_kernel<<<grid, NT>>>(pred, gt, piou, out);
}

// round 6
// speedup vs baseline: 1.1239x; 1.1239x over previous
#include <cuda_runtime.h>
#include <cstdint>

// Problem constants
#define BATCH    16
#define HW       (1024 * 1024)
#define HW4      (HW / 4)
#define GRIDX    37            // 37*16 = 592 = 148 SMs * 4 CTAs -> one exact wave
#define NT       256
#define NQ       8             // g, tg, lg, omp, tomp, t, bin, bint
#define SMOOTH   1e-6f
#define NBLOCKS  (GRIDX * BATCH)

__device__ float        g_part[BATCH * GRIDX * NQ];
__device__ unsigned int g_count;   // zero-init; self-resets each launch

typedef unsigned long long ull;

// ---------- f32x2 packed helpers (Blackwell FFMA2 path) ----------
__device__ __forceinline__ ull pk2(float lo, float hi) {
    ull r; asm("mov.b64 %0, {%1, %2};" : "=l"(r) : "f"(lo), "f"(hi)); return r;
}
__device__ __forceinline__ void upk2(ull v, float& lo, float& hi) {
    asm("mov.b64 {%0, %1}, %2;" : "=f"(lo), "=f"(hi) : "l"(v));
}
__device__ __forceinline__ ull mul2(ull a, ull b) {
    ull r; asm("mul.rn.f32x2 %0, %1, %2;" : "=l"(r) : "l"(a), "l"(b)); return r;
}
__device__ __forceinline__ ull add2(ull a, ull b) {
    ull r; asm("add.rn.f32x2 %0, %1, %2;" : "=l"(r) : "l"(a), "l"(b)); return r;
}
__device__ __forceinline__ ull fma2(ull a, ull b, ull c) {
    ull r; asm("fma.rn.f32x2 %0, %1, %2, %3;" : "=l"(r) : "l"(a), "l"(b), "l"(c)); return r;
}
__device__ __forceinline__ float ex2a(float x) {
    float r; asm("ex2.approx.f32 %0, %1;" : "=f"(r) : "f"(x)); return r;
}
__device__ __forceinline__ float lg2a(float x) {
    float r; asm("lg2.approx.f32 %0, %1;" : "=f"(r) : "f"(x)); return r;
}
__device__ __forceinline__ float rcpa(float x) {
    float r; asm("rcp.approx.f32 %0, %1;" : "=f"(r) : "f"(x)); return r;
}
__device__ __forceinline__ float setgt0(float x) {   // (x > 0) ? 1.0f : 0.0f, fixed-lat pipe
    float r; asm("set.gt.f32.f32 %0, %1, 0f00000000;" : "=f"(r) : "f"(x)); return r;
}

struct Accs { ull g, tg, lg, omp, tomp, t, bin, bint; };

// Per-pair math, t in {0,1}:
//   v = exp((1-2t)x) = 2^(x*log2e*(1-2t)) ; ce = ln2*lg2(1+v) ; omp = 1-p_t = v/(1+v)
//   focal elem = (0.75-0.5t)*ln2*lg2(1+v)*omp^2   (alpha & ln2 folded in epilogue)
//   Sp = omp + t - 2*tomp ; Spt = t - tomp        (recovered in epilogue)
__device__ __forceinline__ void group(Accs& A, float x0, float x1, float t0, float t1,
                                      ull Kp, ull Km2, ull ONE2) {
    ull x2 = pk2(x0, x1);
    ull t2 = pk2(t0, t1);
    ull c2 = fma2(t2, Km2, Kp);          // log2e * (1-2t)
    ull m2 = mul2(x2, c2);
    float m0, m1; upk2(m2, m0, m1);
    float v0 = ex2a(m0), v1 = ex2a(m1);
    ull v2 = pk2(v0, v1);
    ull s2 = add2(v2, ONE2);             // 1+v
    float s0, s1; upk2(s2, s0, s1);
    float r0 = rcpa(s0), r1 = rcpa(s1);
    float l0 = lg2a(s0), l1 = lg2a(s1);
    ull r2 = pk2(r0, r1);
    ull l2 = pk2(l0, l1);
    ull omp2 = mul2(v2, r2);             // v/(1+v)
    ull o2   = mul2(omp2, omp2);
    ull g2   = mul2(l2, o2);             // lg2(1+v)*omp^2
    A.g    = add2(A.g, g2);
    A.tg   = fma2(t2, g2, A.tg);
    A.lg   = add2(A.lg, l2);
    A.omp  = add2(A.omp, omp2);
    A.tomp = fma2(t2, omp2, A.tomp);
    A.t    = add2(A.t, t2);
    ull bin2 = pk2(setgt0(x0), setgt0(x1));
    A.bin  = add2(A.bin, bin2);
    A.bint = fma2(t2, bin2, A.bint);
}

__device__ __forceinline__ float warp_sum(float v) {
    #pragma unroll
    for (int off = 16; off > 0; off >>= 1)
        v += __shfl_xor_sync(0xFFFFFFFFu, v, off);
    return v;
}

__global__ __launch_bounds__(NT, 4)   // 64-reg budget, 4 CTAs/SM, one exact wave
void loss_fused_kernel(const float4* __restrict__ pred,
                       const float4* __restrict__ gt,
                       const float*  __restrict__ pred_iou,
                       float*        __restrict__ out) {
    const int img = blockIdx.y;

    const float LOG2E = 1.4426950408889634f;
    const ull Kp   = pk2(LOG2E, LOG2E);
    const ull Km2  = pk2(-2.0f * LOG2E, -2.0f * LOG2E);
    const ull ONE2 = pk2(1.0f, 1.0f);

    Accs A;
    A.g = A.tg = A.lg = A.omp = A.tomp = A.t = A.bin = A.bint = pk2(0.0f, 0.0f);

    const int stride = GRIDX * NT;
    int i = blockIdx.x * NT + threadIdx.x;
    const float4* px = pred + (size_t)img * HW4 + i;
    const float4* tx = gt   + (size_t)img * HW4 + i;

    // unroll-4: 8 back-to-back LDG.128 in flight per warp (32 KB/SM in flight)
    for (; i + 3 * stride < HW4; i += 4 * stride) {
        float4 a0 = px[0];
        float4 b0 = tx[0];
        float4 a1 = px[stride];
        float4 b1 = tx[stride];
        float4 a2 = px[2 * stride];
        float4 b2 = tx[2 * stride];
        float4 a3 = px[3 * stride];
        float4 b3 = tx[3 * stride];
        px += 4 * stride;
        tx += 4 * stride;
        group(A, a0.x, a0.y, b0.x, b0.y, Kp, Km2, ONE2);
        group(A, a0.z, a0.w, b0.z, b0.w, Kp, Km2, ONE2);
        group(A, a1.x, a1.y, b1.x, b1.y, Kp, Km2, ONE2);
        group(A, a1.z, a1.w, b1.z, b1.w, Kp, Km2, ONE2);
        group(A, a2.x, a2.y, b2.x, b2.y, Kp, Km2, ONE2);
        group(A, a2.z, a2.w, b2.z, b2.w, Kp, Km2, ONE2);
        group(A, a3.x, a3.y, b3.x, b3.y, Kp, Km2, ONE2);
        group(A, a3.z, a3.w, b3.z, b3.w, Kp, Km2, ONE2);
    }
    // remainder (0..3 singles per thread)
    for (; i < HW4; i += stride) {
        float4 a0 = px[0];
        float4 b0 = tx[0];
        px += stride;
        tx += stride;
        group(A, a0.x, a0.y, b0.x, b0.y, Kp, Km2, ONE2);
        group(A, a0.z, a0.w, b0.z, b0.w, Kp, Km2, ONE2);
    }

    // collapse packed halves
    float vals[NQ];
    {
        float lo, hi;
        upk2(A.g,    lo, hi); vals[0] = lo + hi;
        upk2(A.tg,   lo, hi); vals[1] = lo + hi;
        upk2(A.lg,   lo, hi); vals[2] = lo + hi;
        upk2(A.omp,  lo, hi); vals[3] = lo + hi;
        upk2(A.tomp, lo, hi); vals[4] = lo + hi;
        upk2(A.t,    lo, hi); vals[5] = lo + hi;
        upk2(A.bin,  lo, hi); vals[6] = lo + hi;
        upk2(A.bint, lo, hi); vals[7] = lo + hi;
    }

    // -------- block reduction --------
    #pragma unroll
    for (int q = 0; q < NQ; q++) vals[q] = warp_sum(vals[q]);

    __shared__ float sm[NT / 32][NQ];
    const int lane = threadIdx.x & 31;
    const int warp = threadIdx.x >> 5;
    if (lane == 0) {
        #pragma unroll
        for (int q = 0; q < NQ; q++) sm[warp][q] = vals[q];
    }
    __syncthreads();

    __shared__ bool is_last;
    if (warp == 0) {
        #pragma unroll
        for (int q = 0; q < NQ; q++) {
            float v = (lane < NT / 32) ? sm[lane][q] : 0.0f;
            v = warp_sum(v);
            if (lane == 0) vals[q] = v;
        }
        if (lane == 0) {
            float* dst = g_part + ((size_t)img * GRIDX + blockIdx.x) * NQ;
            #pragma unroll
            for (int q = 0; q < NQ; q++) dst[q] = vals[q];
            __threadfence();
            unsigned int v = atomicAdd(&g_count, 1u);
            is_last = (v == (unsigned int)(NBLOCKS - 1));
        }
    }
    __syncthreads();
    if (!is_last) return;

    // -------- epilogue: last block reduces 592 partials --------
    __shared__ float agg[BATCH][4];
    for (int b = warp; b < BATCH; b += NT / 32) {
        float s[NQ] = {0.f, 0.f, 0.f, 0.f, 0.f, 0.f, 0.f, 0.f};
        for (int j = lane; j < GRIDX; j += 32) {
            const float* q = g_part + ((size_t)b * GRIDX + j) * NQ;
            #pragma unroll
            for (int k = 0; k < NQ; k++) s[k] += q[k];
        }
        #pragma unroll
        for (int k = 0; k < NQ; k++) s[k] = warp_sum(s[k]);
        if (lane == 0) {
            // s: 0=g 1=tg 2=lg 3=omp 4=tomp 5=t 6=bin 7=bint
            float Sp  = s[3] + s[5] - 2.0f * s[4];   // sum p
            float Spt = s[5] - s[4];                 // sum p*t
            float dice_term = (2.0f * Spt + SMOOTH) / (Sp + s[5] + SMOOTH);
            float inter  = s[7];
            float uni    = s[6] + s[5] - s[7];
            float actual = (inter + SMOOTH) / (uni + SMOOTH);
            float d = pred_iou[b] - actual;
            agg[b][0] = 0.75f * s[0] - 0.5f * s[1];  // focal partial (x ln2 later)
            agg[b][1] = s[2];                        // sum lg2(1+v)  (x ln2 = sum ce)
            agg[b][2] = dice_term;
            agg[b][3] = d * d;
        }
    }
    __syncthreads();

    if (threadIdx.x == 0) {
        float fsum = 0.f, csum = 0.f, dsum = 0.f, isum = 0.f;
        #pragma unroll
        for (int b = 0; b < BATCH; b++) {
            fsum += agg[b][0];
            csum += agg[b][1];
            dsum += agg[b][2];
            isum += agg[b][3];
        }
        const float LN2  = 0.6931471805599453f;
        const float invN = 1.0f / (float)((long long)BATCH * HW);
        float focal    = LN2 * fsum * invN;
        float dice     = 1.0f - dsum / (float)BATCH;
        float boundary = LN2 * csum * invN;   // mean(ce) = 0.5 * (2*mean(ce))
        float iou_loss = 0.1f * (isum / (float)BATCH);
        out[0] = focal + dice + boundary + iou_loss;
        g_count = 0;   // reset for next graph replay
    }
}

extern "C" void kernel_launch(void* const* d_in, const int* in_sizes, int n_in,
                              void* d_out, int out_size) {
    const float4* pred = (const float4*)d_in[0];
    const float4* gt   = (const float4*)d_in[1];
    const float*  piou = (const float*)d_in[2];
    float* out = (float*)d_out;

    dim3 grid(GRIDX, BATCH);
    loss_fused_kernel<<<grid, NT>>>(pred, gt, piou, out);
}